// round 15
// baseline (speedup 1.0000x reference)
#include <cuda_runtime.h>
#include <cuda_bf16.h>
#include <cstdint>

#define NUTT 64
#define SEQL 512
#define DIM  256
#define G3   768

// ---------------- scratch (__device__ globals; no allocation) --------------
__device__ float g_gx[(size_t)NUTT * SEQL * G3];     // ~100.7 MB
__device__ float g_hh[(size_t)NUTT * SEQL * DIM];    // ~33.6 MB
__device__ float g_utt[NUTT * DIM];

// ---------------- packed f32x2 helpers (Blackwell FFMA2) -------------------
__device__ __forceinline__ unsigned long long pk2(float x, float y) {
    unsigned long long d;
    asm("mov.b64 %0, {%1, %2};" : "=l"(d) : "f"(x), "f"(y));
    return d;
}
__device__ __forceinline__ float2 upk2(unsigned long long v) {
    float2 r;
    asm("mov.b64 {%0, %1}, %2;" : "=f"(r.x), "=f"(r.y) : "l"(v));
    return r;
}
__device__ __forceinline__ unsigned long long fma2(unsigned long long a,
                                                   unsigned long long b,
                                                   unsigned long long c) {
    unsigned long long d;
    asm("fma.rn.f32x2 %0, %1, %2, %3;" : "=l"(d) : "l"(a), "l"(b), "l"(c));
    return d;
}
__device__ __forceinline__ unsigned smem_u32(const void* p) {
    unsigned a;
    asm("{ .reg .u64 t; cvta.to.shared.u64 t, %1; cvt.u32.u64 %0, t; }"
        : "=r"(a) : "l"(p));
    return a;
}
__device__ __forceinline__ unsigned long long lds64(unsigned addr) {
    unsigned long long v;
    asm volatile("ld.shared.b64 %0, [%1];" : "=l"(v) : "r"(addr));
    return v;
}
__device__ __forceinline__ void lds64x2(unsigned addr, unsigned long long& a,
                                        unsigned long long& b) {
    asm volatile("ld.shared.v2.b64 {%0, %1}, [%2];"
                 : "=l"(a), "=l"(b) : "r"(addr));
}
__device__ __forceinline__ void st_cluster_f32(unsigned saddr, unsigned rank, float v) {
    asm volatile(
        "{\n\t"
        ".reg .u32 ra;\n\t"
        "mapa.shared::cluster.u32 ra, %0, %1;\n\t"
        "st.shared::cluster.f32 [ra], %2;\n\t"
        "}" :: "r"(saddr), "r"(rank), "f"(v) : "memory");
}
__device__ __forceinline__ void mbar_init(unsigned addr, unsigned cnt) {
    asm volatile("mbarrier.init.shared.b64 [%0], %1;" :: "r"(addr), "r"(cnt)
                 : "memory");
}
__device__ __forceinline__ void mbar_arrive_cluster(unsigned addr, unsigned rank) {
    asm volatile(
        "{\n\t"
        ".reg .u32 ra;\n\t"
        "mapa.shared::cluster.u32 ra, %0, %1;\n\t"
        "mbarrier.arrive.release.cluster.shared::cluster.b64 _, [ra];\n\t"
        "}" :: "r"(addr), "r"(rank) : "memory");
}
__device__ __forceinline__ void mbar_wait_parity_acq_cluster(unsigned addr,
                                                             unsigned parity) {
    unsigned done;
    asm volatile(
        "{\n\t"
        ".reg .pred p;\n\t"
        "mbarrier.try_wait.parity.acquire.cluster.shared::cta.b64 p, [%1], %2;\n\t"
        "selp.b32 %0, 1, 0, p;\n\t"
        "}" : "=r"(done) : "r"(addr), "r"(parity) : "memory");
    if (!done) {
        asm volatile(
            "{\n\t"
            ".reg .pred P1;\n\t"
            "WL_%=:\n\t"
            "mbarrier.try_wait.parity.acquire.cluster.shared::cta.b64 P1, [%0], %1, 0x989680;\n\t"
            "@P1 bra.uni WD_%=;\n\t"
            "bra.uni WL_%=;\n\t"
            "WD_%=:\n\t"
            "}" :: "r"(addr), "r"(parity) : "memory");
    }
}
__device__ __forceinline__ unsigned my_cluster_rank() {
    unsigned r;
    asm("mov.u32 %0, %%cluster_ctarank;" : "=r"(r));
    return r;
}
__device__ __forceinline__ float sigf(float x) {
    return __fdividef(1.0f, 1.0f + __expf(-x));
}
#define CLUSTER_SYNC_() do { \
    asm volatile("barrier.cluster.arrive.aligned;" ::: "memory"); \
    asm volatile("barrier.cluster.wait.aligned;"   ::: "memory"); } while (0)

// ---------------------------------------------------------------------------
// Kernel 1: g_gx[m][n] = embed[tokens[m]] . Wih[n] + bih[n]
// m in [0,32768), n in [0,768). 64x64 tiles, K in 4 chunks of 64 stored
// k-paired: Xs2[k2][mn] = float2{X[2k2][mn], X[2k2+1][mn]}.
// Conflict-free: microtile strided by 16 (m = i*16+tm, n = j*16+tn).
// ---------------------------------------------------------------------------
__global__ void __launch_bounds__(256)
gx_gemm_kernel(const int* __restrict__ tokens, const float* __restrict__ embed,
               const float* __restrict__ Wih, const float* __restrict__ bih) {
    __shared__ __align__(16) float2 As2[32 * 64];
    __shared__ __align__(16) float2 Bs2[32 * 64];

    const int tid = threadIdx.x;
    const int bm = blockIdx.x, bn = blockIdx.y;

    // loader role: lr = row within tile (warp-contiguous), lq = k quarter
    const int lr = tid & 63;
    const int lq = tid >> 6;
    const int tok = tokens[bm * 64 + lr];
    const float* Arow = embed + (size_t)tok * DIM;
    const float* Brow = Wih + (size_t)(bn * 64 + lr) * DIM;

    // compute role: 4x4 microtile, stride-16
    const int tn = tid & 15;
    const int tm = tid >> 4;
    const unsigned aBase = smem_u32(As2) + (unsigned)tm * 8u;
    const unsigned bBase = smem_u32(Bs2) + (unsigned)tn * 8u;

    unsigned long long acc[4][4];
#pragma unroll
    for (int i = 0; i < 4; i++)
#pragma unroll
        for (int j = 0; j < 4; j++) acc[i][j] = 0ull;

#pragma unroll 1
    for (int kc = 0; kc < 4; kc++) {
        __syncthreads();
#pragma unroll
        for (int s = 0; s < 4; s++) {
            const int kb = lq * 16 + s * 4;
            float4 a = *(const float4*)(Arow + kc * 64 + kb);
            float4 b = *(const float4*)(Brow + kc * 64 + kb);
            As2[(kb >> 1) * 64 + lr]       = make_float2(a.x, a.y);
            As2[((kb >> 1) + 1) * 64 + lr] = make_float2(a.z, a.w);
            Bs2[(kb >> 1) * 64 + lr]       = make_float2(b.x, b.y);
            Bs2[((kb >> 1) + 1) * 64 + lr] = make_float2(b.z, b.w);
        }
        __syncthreads();

#pragma unroll 8
        for (int k2 = 0; k2 < 32; k2++) {
            const unsigned off = (unsigned)k2 * 512u;
            unsigned long long a2[4], b2[4];
#pragma unroll
            for (int i = 0; i < 4; i++) a2[i] = lds64(aBase + off + i * 128u);
#pragma unroll
            for (int j = 0; j < 4; j++) b2[j] = lds64(bBase + off + j * 128u);
#pragma unroll
            for (int i = 0; i < 4; i++)
#pragma unroll
                for (int j = 0; j < 4; j++)
                    acc[i][j] = fma2(a2[i], b2[j], acc[i][j]);
        }
    }

    // epilogue: n = bn*64 + j*16 + tn (16 lanes contiguous per (i,j))
    float bj[4];
#pragma unroll
    for (int j = 0; j < 4; j++) bj[j] = bih[bn * 64 + j * 16 + tn];
#pragma unroll
    for (int i = 0; i < 4; i++) {
        const size_t m = (size_t)bm * 64 + i * 16 + tm;
        float* orow = g_gx + m * G3 + bn * 64 + tn;
#pragma unroll
        for (int j = 0; j < 4; j++) {
            float2 s = upk2(acc[i][j]);
            orow[j * 16] = s.x + s.y + bj[j];
        }
    }
}

// ---------------------------------------------------------------------------
// Kernel 2: word GRU, 512 sequential steps. Cluster of 4 CTAs; CTA owns
// hidden slice [64*rank, 64*rank+64) (gate rows r/z/n). Weights register-
// resident: 384 threads = (row 0..191) x (khalf = lane bit 0), 64 f32x2
// weight regs each. Cluster handles 2 batches. h exchange: st.shared::cluster
// + mbarrier double-buffer (no barrier.cluster in the loop).
// ---------------------------------------------------------------------------
__global__ void __launch_bounds__(384, 1) __cluster_dims__(4, 1, 1)
gru_word_kernel(const float* __restrict__ Whh, const float* __restrict__ bhh) {
    __shared__ __align__(16) float hbuf[2][2][DIM];   // parity, batch, unit
    __shared__ __align__(16) float2 ghb[192];
    __shared__ __align__(16) float2 gxb[192];
    __shared__ __align__(8) unsigned long long mbar[2];

    const int tid = threadIdx.x;
    const unsigned rank = my_cluster_rank();
    const int cid = blockIdx.x >> 2;
    const int b0 = cid * 2, b1 = b0 + 1;

    const int row = tid >> 1;             // local gate row 0..191
    const int kh  = tid & 1;              // k half (lane bit -> shfl reduce)
    const int useg = row >> 6;            // 0:r 1:z 2:n
    const int uu   = row & 63;
    const int grow = useg * 256 + (int)rank * 64 + uu;

    // register-resident weights: 64 packed f32x2 over this thread's k half
    unsigned long long w[64];
    {
        const float2* wr = (const float2*)(Whh + (size_t)grow * DIM + kh * 128);
#pragma unroll
        for (int i = 0; i < 64; i++) {
            float2 v = wr[i];
            w[i] = pk2(v.x, v.y);
        }
    }
    const float bias = bhh[grow];

    const unsigned hbase = smem_u32(hbuf);
    const unsigned mb0 = smem_u32(&mbar[0]);
    const unsigned mb1 = smem_u32(&mbar[1]);

    if (tid == 0) { mbar_init(mb0, 4); mbar_init(mb1, 4); }
    for (int i = tid; i < 2 * DIM; i += 384) ((float*)hbuf[0])[i] = 0.0f;
    __syncthreads();
    CLUSTER_SYNC_();   // once: mbar init + h0 visible cluster-wide

    const float* gx0 = g_gx + (size_t)b0 * SEQL * G3;
    const float* gx1 = g_gx + (size_t)b1 * SEQL * G3;
    float* hh0 = g_hh + (size_t)b0 * SEQL * DIM;
    float* hh1 = g_hh + (size_t)b1 * SEQL * DIM;

    unsigned ph0 = 0, ph1 = 0;   // expected parity for mbar[0], mbar[1]

    for (int t = 0; t < SEQL; t++) {
        const int par = t & 1;

        // prefetch gx for this step (kh==1 threads; consumed post-reduce)
        float xg0 = 0.0f, xg1 = 0.0f;
        if (kh) {
            xg0 = __ldg(gx0 + (size_t)t * G3 + grow);
            xg1 = __ldg(gx1 + (size_t)t * G3 + grow);
        }

        // gemv over this thread's 128-wide k slice, both batches,
        // 2 acc chains per batch, v2.b64 h loads
        unsigned long long a0a = 0ull, a0b = 0ull, a1a = 0ull, a1b = 0ull;
        {
            const unsigned hA = hbase + (unsigned)(par * 2 * DIM) * 4u
                                      + (unsigned)(kh * 128) * 4u;
            const unsigned hB = hA + DIM * 4u;
#pragma unroll
            for (int i = 0; i < 32; i++) {
                unsigned long long p, q;
                lds64x2(hA + i * 16u, p, q);
                a0a = fma2(w[2 * i],     p, a0a);
                a0b = fma2(w[2 * i + 1], q, a0b);
                lds64x2(hB + i * 16u, p, q);
                a1a = fma2(w[2 * i],     p, a1a);
                a1b = fma2(w[2 * i + 1], q, a1b);
            }
        }
        float2 p0 = upk2(fma2(pk2(1.0f, 1.0f), a0a, a0b));
        float2 p1 = upk2(fma2(pk2(1.0f, 1.0f), a1a, a1b));
        float s0 = p0.x + p0.y;
        float s1 = p1.x + p1.y;
        // k-split reduce across lane pair (kh bit)
        s0 += __shfl_xor_sync(0xffffffffu, s0, 1);
        s1 += __shfl_xor_sync(0xffffffffu, s1, 1);

        if (kh == 0) ghb[row] = make_float2(s0 + bias, s1 + bias);
        else         gxb[row] = make_float2(xg0, xg1);
        __syncthreads();

        // gate combine: 128 threads, one (unit, batch) each
        if (tid < 128) {
            const int u = tid & 63;
            const int bi = tid >> 6;
            const float* G = (const float*)ghb;
            const float* X = (const float*)gxb;
            float gr = G[2 * u + bi],         xr = X[2 * u + bi];
            float gz = G[2 * (64 + u) + bi],  xz = X[2 * (64 + u) + bi];
            float gn = G[2 * (128 + u) + bi], xn = X[2 * (128 + u) + bi];

            float r = sigf(xr + gr);
            float z = sigf(xz + gz);
            float n = tanhf(xn + r * gn);
            float hp = hbuf[par][bi][rank * 64 + u];
            float h = (1.0f - z) * n + z * hp;

            // write h into next-parity buffer of ALL 4 CTAs
            const unsigned a = hbase +
                (unsigned)((((par ^ 1) * 2 + bi) * DIM) + (int)rank * 64 + u) * 4u;
#pragma unroll
            for (unsigned rk = 0; rk < 4; rk++) st_cluster_f32(a, rk, h);

            // h history for the attention-pool pass
            float* hh = bi ? hh1 : hh0;
            hh[(size_t)t * DIM + rank * 64 + u] = h;
        }
        __syncthreads();

        // signal: one arrive per source CTA on every CTA's next-parity mbar
        const unsigned mb = par ? mb0 : mb1;   // mbar[par^1]
        if (tid == 0) {
#pragma unroll
            for (unsigned rk = 0; rk < 4; rk++) mbar_arrive_cluster(mb, rk);
        }
        // wait for all 4 CTAs' h slices
        if (par) { mbar_wait_parity_acq_cluster(mb0, ph0); ph0 ^= 1u; }
        else     { mbar_wait_parity_acq_cluster(mb1, ph1); ph1 ^= 1u; }
    }

    CLUSTER_SYNC_();   // keep smem alive until all remote ops landed
}

// ---------------------------------------------------------------------------
// Kernel 3: attention pool over T=512 per batch -> g_utt
// ---------------------------------------------------------------------------
__global__ void __launch_bounds__(256)
pool_kernel(const float* __restrict__ uaw, const float* __restrict__ uab) {
    __shared__ float sw[DIM];
    __shared__ float lg[SEQL];
    __shared__ float rbuf[256];
    __shared__ float sM, sS;

    const int b = blockIdx.x;
    const int tid = threadIdx.x;
    const int wid = tid >> 5, lane = tid & 31;
    const float* H = g_hh + (size_t)b * SEQL * DIM;

    sw[tid] = uaw[tid];
    __syncthreads();

    // logits: one warp per timestep (strided)
    for (int t = wid; t < SEQL; t += 8) {
        const float* h = H + (size_t)t * DIM;
        float s = 0.0f;
#pragma unroll
        for (int j = 0; j < 8; j++)
            s += h[lane + 32 * j] * sw[lane + 32 * j];
#pragma unroll
        for (int o = 16; o > 0; o >>= 1)
            s += __shfl_xor_sync(0xffffffffu, s, o);
        if (lane == 0) lg[t] = s + uab[0];
    }
    __syncthreads();

    float m = fmaxf(lg[tid], lg[tid + 256]);
    rbuf[tid] = m;
    __syncthreads();
    for (int s = 128; s > 0; s >>= 1) {
        if (tid < s) rbuf[tid] = fmaxf(rbuf[tid], rbuf[tid + s]);
        __syncthreads();
    }
    if (tid == 0) sM = rbuf[0];
    __syncthreads();

    float e0 = __expf(lg[tid] - sM);
    float e1 = __expf(lg[tid + 256] - sM);
    __syncthreads();
    lg[tid] = e0;
    lg[tid + 256] = e1;
    rbuf[tid] = e0 + e1;
    __syncthreads();
    for (int s = 128; s > 0; s >>= 1) {
        if (tid < s) rbuf[tid] += rbuf[tid + s];
        __syncthreads();
    }
    if (tid == 0) sS = rbuf[0];
    __syncthreads();

    float acc = 0.0f;
    const float inv = 1.0f / sS;
#pragma unroll 8
    for (int t = 0; t < SEQL; t++)
        acc += lg[t] * H[(size_t)t * DIM + tid];
    g_utt[b * DIM + tid] = acc * inv;
}

// ---------------------------------------------------------------------------
// Kernel 4: sentence GRU (T=1, h0=0 -> gh = bhh; sg_Whh dead) + trivial
// dialog pool (T=1 softmax = identity). out = (1-z)*n.
// Warp-per-row gemv: coalesced W reads, x in registers.
// ---------------------------------------------------------------------------
__global__ void __launch_bounds__(256)
sent_kernel(const float* __restrict__ Wih, const float* __restrict__ bih,
            const float* __restrict__ bhh, float* __restrict__ out) {
    __shared__ float a[G3];
    const int b = blockIdx.x;
    const int tid = threadIdx.x;
    const int wid = tid >> 5, lane = tid & 31;

    // each lane owns x[lane*8 .. lane*8+7] in registers
    const float4* xg = (const float4*)(g_utt + b * DIM);
    float4 xa = xg[lane * 2];
    float4 xb = xg[lane * 2 + 1];

#pragma unroll 2
    for (int r = wid; r < G3; r += 8) {
        const float4* W = (const float4*)(Wih + (size_t)r * DIM) + lane * 2;
        float4 w0 = W[0], w1 = W[1];
        float s = w0.x * xa.x + w0.y * xa.y + w0.z * xa.z + w0.w * xa.w
                + w1.x * xb.x + w1.y * xb.y + w1.z * xb.z + w1.w * xb.w;
#pragma unroll
        for (int o = 16; o > 0; o >>= 1)
            s += __shfl_xor_sync(0xffffffffu, s, o);
        if (lane == 0) a[r] = s + bih[r];
    }
    __syncthreads();

    if (tid < DIM) {
        const int u = tid;
        float r = sigf(a[u] + bhh[u]);
        float z = sigf(a[DIM + u] + bhh[DIM + u]);
        float n = tanhf(a[2 * DIM + u] + r * bhh[2 * DIM + u]);
        out[b * DIM + u] = (1.0f - z) * n;
    }
}

// ---------------------------------------------------------------------------
extern "C" void kernel_launch(void* const* d_in, const int* in_sizes, int n_in,
                              void* d_out, int out_size) {
    const int*   tokens = (const int*)d_in[0];
    const float* embed  = (const float*)d_in[1];
    const float* wgWih  = (const float*)d_in[2];
    const float* wgWhh  = (const float*)d_in[3];
    const float* wgbih  = (const float*)d_in[4];
    const float* wgbhh  = (const float*)d_in[5];
    const float* uaw    = (const float*)d_in[6];
    const float* uab    = (const float*)d_in[7];
    const float* sgWih  = (const float*)d_in[8];
    // d_in[9] = sg_Whh (dead: h0 = 0), d_in[12..13] = da_w/da_b (dead: T=1)
    const float* sgbih  = (const float*)d_in[10];
    const float* sgbhh  = (const float*)d_in[11];
    float* out = (float*)d_out;

    dim3 ggrid(512, 12);
    gx_gemm_kernel<<<ggrid, 256>>>(tokens, embed, wgWih, wgbih);
    gru_word_kernel<<<128, 384>>>(wgWhh, wgbhh);
    pool_kernel<<<NUTT, 256>>>(uaw, uab);
    sent_kernel<<<NUTT, 256>>>(sgWih, sgbih, sgbhh, out);
}

// round 16
// speedup vs baseline: 1.1861x; 1.1861x over previous
#include <cuda_runtime.h>
#include <cuda_bf16.h>
#include <cstdint>

#define NUTT 64
#define SEQL 512
#define DIM  256
#define G3   768

// ---------------- scratch (__device__ globals; no allocation) --------------
__device__ float g_gx[(size_t)NUTT * SEQL * G3];     // ~100.7 MB

// ---------------- packed f32x2 helpers (Blackwell FFMA2) -------------------
__device__ __forceinline__ unsigned long long pk2(float x, float y) {
    unsigned long long d;
    asm("mov.b64 %0, {%1, %2};" : "=l"(d) : "f"(x), "f"(y));
    return d;
}
__device__ __forceinline__ float2 upk2(unsigned long long v) {
    float2 r;
    asm("mov.b64 {%0, %1}, %2;" : "=f"(r.x), "=f"(r.y) : "l"(v));
    return r;
}
__device__ __forceinline__ unsigned long long fma2(unsigned long long a,
                                                   unsigned long long b,
                                                   unsigned long long c) {
    unsigned long long d;
    asm("fma.rn.f32x2 %0, %1, %2, %3;" : "=l"(d) : "l"(a), "l"(b), "l"(c));
    return d;
}
__device__ __forceinline__ unsigned smem_u32(const void* p) {
    unsigned a;
    asm("{ .reg .u64 t; cvta.to.shared.u64 t, %1; cvt.u32.u64 %0, t; }"
        : "=r"(a) : "l"(p));
    return a;
}
__device__ __forceinline__ unsigned long long lds64(unsigned addr) {
    unsigned long long v;
    asm volatile("ld.shared.b64 %0, [%1];" : "=l"(v) : "r"(addr));
    return v;
}
__device__ __forceinline__ void lds64x2(unsigned addr, unsigned long long& a,
                                        unsigned long long& b) {
    asm volatile("ld.shared.v2.b64 {%0, %1}, [%2];"
                 : "=l"(a), "=l"(b) : "r"(addr));
}
__device__ __forceinline__ void st_cluster_f32(unsigned saddr, unsigned rank, float v) {
    asm volatile(
        "{\n\t"
        ".reg .u32 ra;\n\t"
        "mapa.shared::cluster.u32 ra, %0, %1;\n\t"
        "st.shared::cluster.f32 [ra], %2;\n\t"
        "}" :: "r"(saddr), "r"(rank), "f"(v) : "memory");
}
__device__ __forceinline__ unsigned my_cluster_rank() {
    unsigned r;
    asm("mov.u32 %0, %%cluster_ctarank;" : "=r"(r));
    return r;
}
__device__ __forceinline__ float sigf(float x) {
    return __fdividef(1.0f, 1.0f + __expf(-x));
}
// tanh via expf: ~1e-6 rel error (vs 5e-4 for tanh.approx — too risky)
__device__ __forceinline__ float tanhf_fast(float x) {
    float e = __expf(2.0f * x);
    return 1.0f - __fdividef(2.0f, e + 1.0f);
}
#define CLUSTER_SYNC_() do { \
    asm volatile("barrier.cluster.arrive.aligned;" ::: "memory"); \
    asm volatile("barrier.cluster.wait.aligned;"   ::: "memory"); } while (0)

// ---------------------------------------------------------------------------
// Kernel 1: g_gx[m][n] = embed[tokens[m]] . Wih[n] + bih[n]
// m in [0,32768), n in [0,768). 64x64 tiles, K in 4 chunks of 64 stored
// k-paired: Xs2[k2][mn] = float2{X[2k2][mn], X[2k2+1][mn]}.
// Conflict-free microtile: stride-16 (m = i*16+tm, n = j*16+tn).
// ---------------------------------------------------------------------------
__global__ void __launch_bounds__(256)
gx_gemm_kernel(const int* __restrict__ tokens, const float* __restrict__ embed,
               const float* __restrict__ Wih, const float* __restrict__ bih) {
    __shared__ __align__(16) float2 As2[32 * 64];
    __shared__ __align__(16) float2 Bs2[32 * 64];

    const int tid = threadIdx.x;
    const int bm = blockIdx.x, bn = blockIdx.y;

    const int lr = tid & 63;          // loader row (warp-contiguous)
    const int lq = tid >> 6;          // k quarter
    const int tok = tokens[bm * 64 + lr];
    const float* Arow = embed + (size_t)tok * DIM;
    const float* Brow = Wih + (size_t)(bn * 64 + lr) * DIM;

    const int tn = tid & 15;          // compute: 4x4 microtile stride-16
    const int tm = tid >> 4;
    const unsigned aBase = smem_u32(As2) + (unsigned)tm * 8u;
    const unsigned bBase = smem_u32(Bs2) + (unsigned)tn * 8u;

    unsigned long long acc[4][4];
#pragma unroll
    for (int i = 0; i < 4; i++)
#pragma unroll
        for (int j = 0; j < 4; j++) acc[i][j] = 0ull;

#pragma unroll 1
    for (int kc = 0; kc < 4; kc++) {
        __syncthreads();
#pragma unroll
        for (int s = 0; s < 4; s++) {
            const int kb = lq * 16 + s * 4;
            float4 a = *(const float4*)(Arow + kc * 64 + kb);
            float4 b = *(const float4*)(Brow + kc * 64 + kb);
            As2[(kb >> 1) * 64 + lr]       = make_float2(a.x, a.y);
            As2[((kb >> 1) + 1) * 64 + lr] = make_float2(a.z, a.w);
            Bs2[(kb >> 1) * 64 + lr]       = make_float2(b.x, b.y);
            Bs2[((kb >> 1) + 1) * 64 + lr] = make_float2(b.z, b.w);
        }
        __syncthreads();

#pragma unroll 8
        for (int k2 = 0; k2 < 32; k2++) {
            const unsigned off = (unsigned)k2 * 512u;
            unsigned long long a2[4], b2[4];
#pragma unroll
            for (int i = 0; i < 4; i++) a2[i] = lds64(aBase + off + i * 128u);
#pragma unroll
            for (int j = 0; j < 4; j++) b2[j] = lds64(bBase + off + j * 128u);
#pragma unroll
            for (int i = 0; i < 4; i++)
#pragma unroll
                for (int j = 0; j < 4; j++)
                    acc[i][j] = fma2(a2[i], b2[j], acc[i][j]);
        }
    }

    float bj[4];
#pragma unroll
    for (int j = 0; j < 4; j++) bj[j] = bih[bn * 64 + j * 16 + tn];
#pragma unroll
    for (int i = 0; i < 4; i++) {
        const size_t m = (size_t)bm * 64 + i * 16 + tm;
        float* orow = g_gx + m * G3 + bn * 64 + tn;
#pragma unroll
        for (int j = 0; j < 4; j++) {
            float2 s = upk2(acc[i][j]);
            orow[j * 16] = s.x + s.y + bj[j];
        }
    }
}

// ---------------------------------------------------------------------------
// Kernel 2 (FUSED): word GRU 512 steps + ONLINE attention pool + sentence GRU
// tail. Cluster of 4 CTAs; CTA rank owns hidden units [64r, 64r+64) =
// gate rows {U, 256+U, 512+U}. Weights register-resident: 384 threads =
// (row 0..191) x (khalf = lane bit 0), 64 f32x2 regs each. 2 batches/cluster.
// h exchange: st.shared::cluster + barrier.cluster (R14-proven protocol).
// Pool: warps 0/1 compute logit dot per step; online softmax (m,s) in lane 0;
// combine threads keep per-unit rescaled accumulators in registers.
// ---------------------------------------------------------------------------
__global__ void __launch_bounds__(384, 1) __cluster_dims__(4, 1, 1)
gru_fused_kernel(const float* __restrict__ Whh, const float* __restrict__ bhh,
                 const float* __restrict__ uaw,
                 const float* __restrict__ sgWih, const float* __restrict__ sgbih,
                 const float* __restrict__ sgbhh, float* __restrict__ out) {
    __shared__ __align__(16) float hbuf[2][2][DIM];   // parity, batch, unit
    __shared__ __align__(16) float2 ghb[192];
    __shared__ __align__(16) float2 gxb[192];
    __shared__ __align__(16) float swua[DIM];
    __shared__ float2 pc[2];          // per-batch (c_old, c_new) softmax scales
    __shared__ float  sS[2];          // final softmax sums

    const int tid = threadIdx.x;
    const int wid = tid >> 5, lane = tid & 31;
    const unsigned rank = my_cluster_rank();
    const int cid = blockIdx.x >> 2;
    const int b0 = cid * 2;

    const int row = tid >> 1;             // local gate row 0..191
    const int kh  = tid & 1;              // k half (lane bit -> shfl reduce)
    const int useg = row >> 6;            // 0:r 1:z 2:n
    const int uu   = row & 63;
    const int grow = useg * 256 + (int)rank * 64 + uu;

    // register-resident weights (this thread's 128-wide k slice, packed)
    unsigned long long w[64];
    {
        const float2* wr = (const float2*)(Whh + (size_t)grow * DIM + kh * 128);
#pragma unroll
        for (int i = 0; i < 64; i++) {
            float2 v = wr[i];
            w[i] = pk2(v.x, v.y);
        }
    }
    const float bias = bhh[grow];

    const unsigned hbase = smem_u32(hbuf);

    for (int i = tid; i < 2 * DIM; i += 384) ((float*)hbuf[0])[i] = 0.0f;
    if (tid < DIM) swua[tid] = uaw[tid];
    __syncthreads();
    CLUSTER_SYNC_();

    const float* gp0 = g_gx + (size_t)b0 * SEQL * G3 + grow;
    const float* gp1 = gp0 + (size_t)SEQL * G3;

    // online softmax state (meaningful in lane 0 of warps 0/1)
    float pm = -1e30f, ps = 0.0f;
    // pooled accumulator (meaningful in tid<128: unit = rank*64+(tid&63),
    // batch = tid>>6)
    float pacc = 0.0f;

    for (int t = 0; t < SEQL; t++) {
        const int par = t & 1;

        // prefetch gx (kh==1 threads; consumed ~900 cyc later)
        float xg0 = 0.0f, xg1 = 0.0f;
        if (kh) { xg0 = __ldg(gp0); xg1 = __ldg(gp1); }
        gp0 += G3; gp1 += G3;

        // gemv: 2 acc chains per batch, broadcast LDS.128 h loads
        unsigned long long a0a = 0ull, a0b = 0ull, a1a = 0ull, a1b = 0ull;
        {
            const unsigned hA = hbase + (unsigned)(par * 2 * DIM + kh * 128) * 4u;
            const unsigned hB = hA + DIM * 4u;
#pragma unroll
            for (int i = 0; i < 32; i++) {
                unsigned long long p, q;
                lds64x2(hA + i * 16u, p, q);
                a0a = fma2(w[2 * i],     p, a0a);
                a0b = fma2(w[2 * i + 1], q, a0b);
                lds64x2(hB + i * 16u, p, q);
                a1a = fma2(w[2 * i],     p, a1a);
                a1b = fma2(w[2 * i + 1], q, a1b);
            }
        }
        float2 p0 = upk2(fma2(pk2(1.0f, 1.0f), a0a, a0b));
        float2 p1 = upk2(fma2(pk2(1.0f, 1.0f), a1a, a1b));
        float s0 = p0.x + p0.y;
        float s1 = p1.x + p1.y;
        s0 += __shfl_xor_sync(0xffffffffu, s0, 1);
        s1 += __shfl_xor_sync(0xffffffffu, s1, 1);

        // online-pool logit for h_t (the state read this step); skip h_0 = 0
        if (t > 0 && wid < 2) {
            const float* hb = &hbuf[par][wid][0];
            float l = 0.0f;
#pragma unroll
            for (int j = 0; j < 8; j++)
                l += hb[lane * 8 + j] * swua[lane * 8 + j];
#pragma unroll
            for (int o = 16; o > 0; o >>= 1)
                l += __shfl_xor_sync(0xffffffffu, l, o);
            if (lane == 0) {
                float mn = fmaxf(pm, l);
                float c0 = __expf(pm - mn);
                float c1 = __expf(l - mn);
                ps = ps * c0 + c1;
                pm = mn;
                pc[wid] = make_float2(c0, c1);
            }
        }

        if (kh == 0) ghb[row] = make_float2(s0 + bias, s1 + bias);
        else         gxb[row] = make_float2(xg0, xg1);
        __syncthreads();

        // gate combine + pool accumulate: 128 threads, one (unit, batch) each
        if (tid < 128) {
            const int u = tid & 63;
            const int bi = tid >> 6;
            const float* G = (const float*)ghb;
            const float* X = (const float*)gxb;
            float gr = G[2 * u + bi],          xr = X[2 * u + bi];
            float gz = G[2 * (64 + u) + bi],   xz = X[2 * (64 + u) + bi];
            float gn = G[2 * (128 + u) + bi],  xn = X[2 * (128 + u) + bi];

            float r = sigf(xr + gr);
            float z = sigf(xz + gz);
            float n = tanhf_fast(xn + r * gn);
            float hp = hbuf[par][bi][rank * 64 + u];
            float h = (1.0f - z) * n + z * hp;

            if (t > 0) {
                float2 c = pc[bi];
                pacc = pacc * c.x + c.y * hp;
            }

            // write h into next-parity buffer of ALL 4 CTAs
            const unsigned a = hbase +
                (unsigned)((((par ^ 1) * 2 + bi) * DIM) + (int)rank * 64 + u) * 4u;
#pragma unroll
            for (unsigned rk = 0; rk < 4; rk++) st_cluster_f32(a, rk, h);
        }
        CLUSTER_SYNC_();
    }

    // ---- final pool term: h_512 lives in hbuf[0] ----
    if (wid < 2) {
        const float* hb = &hbuf[0][wid][0];
        float l = 0.0f;
#pragma unroll
        for (int j = 0; j < 8; j++)
            l += hb[lane * 8 + j] * swua[lane * 8 + j];
#pragma unroll
        for (int o = 16; o > 0; o >>= 1)
            l += __shfl_xor_sync(0xffffffffu, l, o);
        if (lane == 0) {
            float mn = fmaxf(pm, l);
            float c0 = __expf(pm - mn);
            float c1 = __expf(l - mn);
            ps = ps * c0 + c1;
            pc[wid] = make_float2(c0, c1);
            sS[wid] = ps;
        }
    }
    __syncthreads();

    // finalize utt and broadcast into hbuf[1] of all 4 CTAs
    if (tid < 128) {
        const int u = tid & 63;
        const int bi = tid >> 6;
        float hp = hbuf[0][bi][rank * 64 + u];
        float2 c = pc[bi];
        pacc = pacc * c.x + c.y * hp;
        float utt = __fdividef(pacc, sS[bi]);
        const unsigned a = hbase +
            (unsigned)((2 + bi) * DIM + (int)rank * 64 + u) * 4u;  // hbuf[1][bi]
#pragma unroll
        for (unsigned rk = 0; rk < 4; rk++) st_cluster_f32(a, rk, utt);
    }
    CLUSTER_SYNC_();

    // ---- sentence GRU tail (sg_Whh dead: h0=0 -> gh=bhh; T=1 pool=identity)
    {
        const float* xs0 = &hbuf[1][0][0];
        const float* xs1 = &hbuf[1][1][0];
        const float4* Wr = (const float4*)(sgWih + (size_t)grow * DIM + kh * 128);
        float a0 = 0.0f, a1 = 0.0f;
#pragma unroll 8
        for (int i = 0; i < 32; i++) {
            float4 w4 = __ldg(Wr + i);
            const int k0 = kh * 128 + i * 4;
            a0 += w4.x * xs0[k0] + w4.y * xs0[k0 + 1]
                + w4.z * xs0[k0 + 2] + w4.w * xs0[k0 + 3];
            a1 += w4.x * xs1[k0] + w4.y * xs1[k0 + 1]
                + w4.z * xs1[k0 + 2] + w4.w * xs1[k0 + 3];
        }
        a0 += __shfl_xor_sync(0xffffffffu, a0, 1);
        a1 += __shfl_xor_sync(0xffffffffu, a1, 1);
        if (kh == 0) {
            float bg = sgbih[grow];
            ghb[row] = make_float2(a0 + bg, a1 + bg);
        }
    }
    __syncthreads();

    if (tid < 128) {
        const int u = tid & 63;
        const int bi = tid >> 6;
        const int U = (int)rank * 64 + u;
        const float* G = (const float*)ghb;
        float ar = G[2 * u + bi];
        float az = G[2 * (64 + u) + bi];
        float an = G[2 * (128 + u) + bi];
        float r = sigf(ar + sgbhh[U]);
        float z = sigf(az + sgbhh[DIM + U]);
        float n = tanhf_fast(an + r * sgbhh[2 * DIM + U]);
        out[(b0 + bi) * DIM + U] = (1.0f - z) * n;
    }
    CLUSTER_SYNC_();   // keep smem alive until peers' remote ops landed
}

// ---------------------------------------------------------------------------
extern "C" void kernel_launch(void* const* d_in, const int* in_sizes, int n_in,
                              void* d_out, int out_size) {
    const int*   tokens = (const int*)d_in[0];
    const float* embed  = (const float*)d_in[1];
    const float* wgWih  = (const float*)d_in[2];
    const float* wgWhh  = (const float*)d_in[3];
    const float* wgbih  = (const float*)d_in[4];
    const float* wgbhh  = (const float*)d_in[5];
    const float* uaw    = (const float*)d_in[6];
    // d_in[7] = ua_b (dead: softmax shift-invariant)
    const float* sgWih  = (const float*)d_in[8];
    // d_in[9] = sg_Whh (dead: h0 = 0), d_in[12..13] = da_w/da_b (dead: T=1)
    const float* sgbih  = (const float*)d_in[10];
    const float* sgbhh  = (const float*)d_in[11];
    float* out = (float*)d_out;

    dim3 ggrid(512, 12);
    gx_gemm_kernel<<<ggrid, 256>>>(tokens, embed, wgWih, wgbih);
    gru_fused_kernel<<<128, 384>>>(wgWhh, wgbhh, uaw, sgWih, sgbih, sgbhh, out);
}